// round 16
// baseline (speedup 1.0000x reference)
#include <cuda_runtime.h>
#include <cuda_fp16.h>

// ---------------------------------------------------------------------------
// out[m,n] = sum_r sum_k A[r,m,k] * W[r,n,k]   (M=N=4096, K=8*1024)
// fp32 in/out, fp16 single-pass mma.sync.m16n8k16 (f32 accumulate).
// R16: R14 champion (CTA 256x128, 16 warps of 64x32, split-K=2, atomicAdd)
// with K-chunk doubled to 128 and a 2-stage ring: one wait_group + one
// __syncthreads per 128 K (half R14's sync rate), fully overlapped since
// issue(ic+1) has all of compute(ic) to complete. cvt+zero fused.
// ---------------------------------------------------------------------------

using u32 = unsigned int;

static constexpr int NT      = 4096;       // N total (also M total)
static constexpr int KL      = 1024;       // K per rank slab
static constexpr int KC      = 128;        // K per chunk
static constexpr int NCH_H   = 32;         // chunks per split (half of 64)
static constexpr int R_B     = 65536;      // B region offset within a stage
static constexpr int STAGE   = 98304;      // A 64KB + B 32KB (fp16)
static constexpr int NSTG    = 2;
static constexpr int SMEM_TOTAL = NSTG * STAGE;          // 192 KB
static constexpr size_t NA   = (size_t)8 * NT * KL;      // elems per tensor

// fp16 scratch: A at [0, NA), W at [NA, 2*NA)  (128 MB)
__device__ __half g_fp16[2 * NA];

// ---------------- convert pass (also zeroes the poisoned output) ----------
__global__ __launch_bounds__(256) void cvt_kernel(const float* __restrict__ A,
                                                  const float* __restrict__ W,
                                                  float4* __restrict__ out4)
{
    const size_t total8 = (2 * NA) / 8;
    const size_t stride = (size_t)gridDim.x * blockDim.x;
    for (size_t g = (size_t)blockIdx.x * blockDim.x + threadIdx.x;
         g < total8; g += stride) {
        const size_t off = g * 8;
        const float* src = (off < NA) ? (A + off) : (W + (off - NA));
        const float4 v0 = *reinterpret_cast<const float4*>(src);
        const float4 v1 = *reinterpret_cast<const float4*>(src + 4);
        const __half2 h0 = __floats2half2_rn(v0.x, v0.y);
        const __half2 h1 = __floats2half2_rn(v0.z, v0.w);
        const __half2 h2 = __floats2half2_rn(v1.x, v1.y);
        const __half2 h3 = __floats2half2_rn(v1.z, v1.w);
        uint4 pk;
        pk.x = *(const u32*)&h0; pk.y = *(const u32*)&h1;
        pk.z = *(const u32*)&h2; pk.w = *(const u32*)&h3;
        *reinterpret_cast<uint4*>(&g_fp16[off]) = pk;
    }
    const size_t ztotal = (size_t)NT * NT / 4;
    for (size_t g = (size_t)blockIdx.x * blockDim.x + threadIdx.x;
         g < ztotal; g += stride)
        out4[g] = make_float4(0.f, 0.f, 0.f, 0.f);
}

// ---------------- GEMM ----------------
static __device__ __forceinline__ u32 smem_u32(const void* p) {
    u32 a;
    asm("{ .reg .u64 t; cvta.to.shared.u64 t, %1; cvt.u32.u64 %0, t; }"
        : "=r"(a) : "l"(p));
    return a;
}

static __device__ __forceinline__ void ldsm4(u32 addr, u32* r) {
    asm volatile("ldmatrix.sync.aligned.m8n8.x4.shared.b16 {%0,%1,%2,%3}, [%4];"
                 : "=r"(r[0]), "=r"(r[1]), "=r"(r[2]), "=r"(r[3]) : "r"(addr));
}

static __device__ __forceinline__ void mma16816(float* c, const u32* a,
                                                u32 b0, u32 b1) {
    asm volatile(
        "mma.sync.aligned.m16n8k16.row.col.f32.f16.f16.f32 "
        "{%0,%1,%2,%3}, {%4,%5,%6,%7}, {%8,%9}, {%0,%1,%2,%3};"
        : "+f"(c[0]), "+f"(c[1]), "+f"(c[2]), "+f"(c[3])
        : "r"(a[0]), "r"(a[1]), "r"(a[2]), "r"(a[3]), "r"(b0), "r"(b1));
}

static __device__ __forceinline__ void cp16(u32 sdst, const void* gsrc) {
    asm volatile("cp.async.cg.shared.global [%0], [%1], 16;"
                 :: "r"(sdst), "l"(gsrc) : "memory");
}

__global__ __launch_bounds__(512, 1)
void gemm_rs_kernel(float* __restrict__ out)
{
    extern __shared__ char smem[];
    const u32 sb  = smem_u32(smem);
    const int tid = threadIdx.x;
    const int lane = tid & 31;
    const int w    = tid >> 5;

    // Grid: 1024 = 512 tiles x 2 K-splits. Tile raster identical to R14:
    // groups of 8 M-tiles x 32 N-tiles.
    const int lin   = blockIdx.x & 511;
    const int split = blockIdx.x >> 9;         // 0 or 1
    const int grp = lin >> 8;                  // 0..1
    const int rem = lin & 255;
    const int m0  = ((grp << 3) + (rem & 7)) << 8;   // * 256
    const int n0  = (rem >> 3) << 7;                 // * 128
    const int ic0 = split * NCH_H;             // global chunk base

    // ---- cp.async thread maps (rows of 16 chunks x 16B = 256B) ----
    // A: 256 rows x 16 chunks -> 8 chunks per thread
    const int aRow = tid >> 1;                 // 0..255
    const int ajb  = (tid & 1) << 3;           // 0 or 8
    // B: 128 rows x 16 chunks -> 4 chunks per thread
    const int bRow = tid >> 2;                 // 0..127
    const int bjb  = (tid & 3) << 2;           // 0,4,8,12
    const __half* gA = g_fp16 + (size_t)(m0 + aRow) * KL + (size_t)ajb * 8;
    const __half* gB = g_fp16 + NA + (size_t)(n0 + bRow) * KL + (size_t)bjb * 8;
    const u32 sRowA = (u32)aRow * 256;
    const u32 sRowB = (u32)bRow * 256;
    u32 swzA[8], swzB[4];
    #pragma unroll
    for (int j2 = 0; j2 < 8; ++j2)
        swzA[j2] = (u32)(((ajb + j2) ^ (aRow & 7)) << 4);
    #pragma unroll
    for (int j2 = 0; j2 < 4; ++j2)
        swzB[j2] = (u32)(((bjb + j2) ^ (bRow & 7)) << 4);

    // ---- ldmatrix per-lane bases: warp grid 4(M) x 4(N), tile 64x32 ----
    const int wm = (w >> 2) << 6;              // 0,64,128,192
    const int wn = (w & 3) << 5;               // 0,32,64,96
    const u32 raA = (u32)(wm + (lane & 15)) * 256;
    const u32 raB = (u32)(wn + (lane & 15)) * 256 + R_B;
    const u32 khalf = (u32)(lane >> 4);
    const u32 l7    = (u32)(lane & 7);

    float c[4][4][4] = {};
    u32 ah[2][4][4], bh[2][2][4];

    // ic is the LOCAL chunk index within this split (0..31).
    auto issue = [&](int ic) {
        if (ic < NCH_H) {
            const int icg = ic0 + ic;          // global chunk
            const u32 sdst = sb + (u32)(ic & 1) * STAGE;
            const size_t kbase = (size_t)(icg >> 3) * ((size_t)NT * KL)
                               + (size_t)((icg & 7) * KC);
            const __half* pa = gA + kbase;
            const __half* pb = gB + kbase;
            #pragma unroll
            for (int j2 = 0; j2 < 8; ++j2)
                cp16(sdst + sRowA + swzA[j2], pa + j2 * 8);
            #pragma unroll
            for (int j2 = 0; j2 < 4; ++j2)
                cp16(sdst + R_B + sRowB + swzB[j2], pb + j2 * 8);
        }
        asm volatile("cp.async.commit_group;" ::: "memory");
    };

    auto ldsm_kk = [&](u32 base, int kk, int fb) {
        const u32 off = (((u32)(2 * kk) + khalf) ^ l7) << 4;
        const u32 pa = base + raA + off;
        const u32 pb = base + raB + off;
        #pragma unroll
        for (int t = 0; t < 4; ++t) ldsm4(pa + (u32)t * 4096, ah[fb][t]);
        #pragma unroll
        for (int t = 0; t < 2; ++t) ldsm4(pb + (u32)t * 4096, bh[fb][t]);
    };

    // ---- prologue: stage chunk 0 of this split ----
    issue(0);

    #pragma unroll 1
    for (int ic = 0; ic < NCH_H; ++ic) {
        const u32 base = sb + (u32)(ic & 1) * STAGE;

        // wait_group 0: chunk ic complete. Barrier then fences all readers
        // of slot (ic+1)&1 (chunk ic-1, fully consumed last iteration)
        // before issue() below overwrites it.
        asm volatile("cp.async.wait_group 0;" ::: "memory");
        __syncthreads();

        issue(ic + 1);

        ldsm_kk(base, 0, 0);
        #pragma unroll
        for (int kk = 0; kk < 8; ++kk) {       // 8 K16 blocks per K128 chunk
            const int fb = kk & 1;
            if (kk < 7) ldsm_kk(base, kk + 1, fb ^ 1);   // prefetch next block

            // mt -> j: same-accumulator dep distance = 16 MMAs
            #pragma unroll
            for (int mt = 0; mt < 4; ++mt) {
                #pragma unroll
                for (int j = 0; j < 4; ++j) {
                    const int t = j >> 1, s = j & 1;
                    mma16816(c[mt][j], ah[fb][mt], bh[fb][t][s], bh[fb][t][s + 2]);
                }
            }
        }
    }

    // ---- epilogue: atomic accumulate (two split contributors per tile) ----
    const int orow = m0 + wm + (lane >> 2);
    const int ocol = n0 + wn + ((lane & 3) << 1);
    #pragma unroll
    for (int mt = 0; mt < 4; ++mt) {
        #pragma unroll
        for (int j = 0; j < 4; ++j) {
            float* p = out + (size_t)(orow + mt * 16) * NT + (ocol + j * 8);
            atomicAdd(p,     c[mt][j][0]);
            atomicAdd(p + 1, c[mt][j][1]);
            atomicAdd(p + (size_t)8 * NT,     c[mt][j][2]);
            atomicAdd(p + (size_t)8 * NT + 1, c[mt][j][3]);
        }
    }
}

extern "C" void kernel_launch(void* const* d_in, const int* in_sizes, int n_in,
                              void* d_out, int out_size)
{
    const float* A = (const float*)d_in[0];   // [8, 4096, 1024]
    const float* W = (const float*)d_in[1];   // [8, 4096, 1024]
    float* out = (float*)d_out;               // [8, 512, 4096] == [4096, 4096]

    cvt_kernel<<<4096, 256>>>(A, W, (float4*)out);

    cudaFuncSetAttribute(gemm_rs_kernel,
                         cudaFuncAttributeMaxDynamicSharedMemorySize, SMEM_TOTAL);
    gemm_rs_kernel<<<1024, 512, SMEM_TOTAL>>>(out);
}

// round 17
// speedup vs baseline: 1.4343x; 1.4343x over previous
#include <cuda_runtime.h>
#include <cuda_fp16.h>

// ---------------------------------------------------------------------------
// out[m,n] = sum_r sum_k A[r,m,k] * W[r,n,k]   (M=N=4096, K=8*1024)
// fp32 in/out, fp16 single-pass mma.sync.m16n8k16 (f32 accumulate).
// R17: R14 champion shape (CTA 256x128, 16 warps of 64x32, K-chunk 64,
// 4-stage cp.async ring, split-K=2) with the per-chunk __syncthreads
// replaced by per-slot mbarrier producer/consumer tracking:
//   full[s]:  count 512, cp.async.mbarrier.arrive.noinc per thread
//   empty[s]: count 16,  one mbarrier.arrive per warp after consuming
// Warps decouple: a warp only blocks when >3 chunks ahead of the slowest,
// instead of re-paying warp skew at a CTA barrier every chunk.
// ---------------------------------------------------------------------------

using u32 = unsigned int;

static constexpr int NT      = 4096;       // N total (also M total)
static constexpr int KL      = 1024;       // K per rank slab
static constexpr int NCH_H   = 64;         // chunks per split (half of 128)
static constexpr int R_B     = 32768;      // B region offset within a stage
static constexpr int STAGE   = 49152;      // A 32KB + B 16KB (fp16)
static constexpr int SM_DATA = 1024;       // data region offset (mbarriers below)
static constexpr int SMEM_TOTAL = SM_DATA + 4 * STAGE;   // 197632
static constexpr size_t NA   = (size_t)8 * NT * KL;      // elems per tensor

// fp16 scratch: A at [0, NA), W at [NA, 2*NA)  (128 MB)
__device__ __half g_fp16[2 * NA];

// ---------------- convert pass (also zeroes the poisoned output) ----------
__global__ __launch_bounds__(256) void cvt_kernel(const float* __restrict__ A,
                                                  const float* __restrict__ W,
                                                  float4* __restrict__ out4)
{
    const size_t total8 = (2 * NA) / 8;
    const size_t stride = (size_t)gridDim.x * blockDim.x;
    for (size_t g = (size_t)blockIdx.x * blockDim.x + threadIdx.x;
         g < total8; g += stride) {
        const size_t off = g * 8;
        const float* src = (off < NA) ? (A + off) : (W + (off - NA));
        const float4 v0 = *reinterpret_cast<const float4*>(src);
        const float4 v1 = *reinterpret_cast<const float4*>(src + 4);
        const __half2 h0 = __floats2half2_rn(v0.x, v0.y);
        const __half2 h1 = __floats2half2_rn(v0.z, v0.w);
        const __half2 h2 = __floats2half2_rn(v1.x, v1.y);
        const __half2 h3 = __floats2half2_rn(v1.z, v1.w);
        uint4 pk;
        pk.x = *(const u32*)&h0; pk.y = *(const u32*)&h1;
        pk.z = *(const u32*)&h2; pk.w = *(const u32*)&h3;
        *reinterpret_cast<uint4*>(&g_fp16[off]) = pk;
    }
    const size_t ztotal = (size_t)NT * NT / 4;
    for (size_t g = (size_t)blockIdx.x * blockDim.x + threadIdx.x;
         g < ztotal; g += stride)
        out4[g] = make_float4(0.f, 0.f, 0.f, 0.f);
}

// ---------------- GEMM ----------------
static __device__ __forceinline__ u32 smem_u32(const void* p) {
    u32 a;
    asm("{ .reg .u64 t; cvta.to.shared.u64 t, %1; cvt.u32.u64 %0, t; }"
        : "=r"(a) : "l"(p));
    return a;
}

static __device__ __forceinline__ void ldsm4(u32 addr, u32* r) {
    asm volatile("ldmatrix.sync.aligned.m8n8.x4.shared.b16 {%0,%1,%2,%3}, [%4];"
                 : "=r"(r[0]), "=r"(r[1]), "=r"(r[2]), "=r"(r[3]) : "r"(addr));
}

static __device__ __forceinline__ void mma16816(float* c, const u32* a,
                                                u32 b0, u32 b1) {
    asm volatile(
        "mma.sync.aligned.m16n8k16.row.col.f32.f16.f16.f32 "
        "{%0,%1,%2,%3}, {%4,%5,%6,%7}, {%8,%9}, {%0,%1,%2,%3};"
        : "+f"(c[0]), "+f"(c[1]), "+f"(c[2]), "+f"(c[3])
        : "r"(a[0]), "r"(a[1]), "r"(a[2]), "r"(a[3]), "r"(b0), "r"(b1));
}

static __device__ __forceinline__ void cp16(u32 sdst, const void* gsrc) {
    asm volatile("cp.async.cg.shared.global [%0], [%1], 16;"
                 :: "r"(sdst), "l"(gsrc) : "memory");
}

static __device__ __forceinline__ void mbar_init(u32 mbar, u32 cnt) {
    asm volatile("mbarrier.init.shared.b64 [%0], %1;" :: "r"(mbar), "r"(cnt) : "memory");
}
static __device__ __forceinline__ void mbar_arrive(u32 mbar) {
    asm volatile("mbarrier.arrive.shared.b64 _, [%0];" :: "r"(mbar) : "memory");
}
static __device__ __forceinline__ void cp_arrive(u32 mbar) {
    asm volatile("cp.async.mbarrier.arrive.noinc.shared.b64 [%0];"
                 :: "r"(mbar) : "memory");
}
static __device__ __forceinline__ void mbar_wait(u32 mbar, u32 parity) {
    u32 done;
    asm volatile(
        "{\n\t.reg .pred p;\n\t"
        "mbarrier.try_wait.parity.acquire.cta.shared::cta.b64 p, [%1], %2;\n\t"
        "selp.b32 %0, 1, 0, p;\n\t}"
        : "=r"(done) : "r"(mbar), "r"(parity) : "memory");
    while (!done) {
        asm volatile(
            "{\n\t.reg .pred p;\n\t"
            "mbarrier.try_wait.parity.acquire.cta.shared::cta.b64 p, [%1], %2, 0x989680;\n\t"
            "selp.b32 %0, 1, 0, p;\n\t}"
            : "=r"(done) : "r"(mbar), "r"(parity) : "memory");
    }
}

__global__ __launch_bounds__(512, 1)
void gemm_rs_kernel(float* __restrict__ out)
{
    extern __shared__ char smem[];
    const u32 sb  = smem_u32(smem);
    const int tid = threadIdx.x;
    const int lane = tid & 31;
    const int w    = tid >> 5;

    // Grid: 1024 = 512 tiles x 2 K-splits; raster = groups of 8 M x 32 N.
    const int lin   = blockIdx.x & 511;
    const int split = blockIdx.x >> 9;         // 0 or 1
    const int grp = lin >> 8;                  // 0..1
    const int rem = lin & 255;
    const int m0  = ((grp << 3) + (rem & 7)) << 8;   // * 256
    const int n0  = (rem >> 3) << 7;                 // * 128
    const int ic0 = split * NCH_H;             // global chunk base

    // mbarriers: full[s] at sb + s*8, empty[s] at sb + 32 + s*8
    if (tid == 0) {
        #pragma unroll
        for (int s = 0; s < 4; ++s) {
            mbar_init(sb + s * 8, 512);        // full: one cp-arrive per thread
            mbar_init(sb + 32 + s * 8, 16);    // empty: one arrive per warp
        }
    }
    __syncthreads();

    // ---- cp.async thread maps ----
    const int aRow = tid >> 1;                 // 0..255
    const int ajb  = (tid & 1) << 2;           // 0 or 4
    const int bRow = tid >> 2;                 // 0..127
    const int bjb  = (tid & 3) << 1;           // 0,2,4,6
    const __half* gA = g_fp16 + (size_t)(m0 + aRow) * KL + (size_t)ajb * 8;
    const __half* gB = g_fp16 + NA + (size_t)(n0 + bRow) * KL + (size_t)bjb * 8;
    const u32 sRowA = (u32)aRow * 128;
    const u32 sRowB = (u32)bRow * 128;
    u32 swzA[4], swzB[2];
    #pragma unroll
    for (int j2 = 0; j2 < 4; ++j2)
        swzA[j2] = (u32)(((ajb + j2) ^ (aRow & 7)) << 4);
    #pragma unroll
    for (int j2 = 0; j2 < 2; ++j2)
        swzB[j2] = (u32)(((bjb + j2) ^ (bRow & 7)) << 4);

    // ---- ldmatrix per-lane bases: warp grid 4(M) x 4(N), tile 64x32 ----
    const int wm = (w >> 2) << 6;              // 0,64,128,192
    const int wn = (w & 3) << 5;               // 0,32,64,96
    const u32 raA = (u32)(wm + (lane & 15)) * 128;
    const u32 raB = (u32)(wn + (lane & 15)) * 128 + R_B;
    const u32 khalf = (u32)(lane >> 4);
    const u32 l7    = (u32)(lane & 7);

    float c[4][4][4] = {};
    u32 ah[2][4][4], bh[2][2][4];

    // Produce chunk j (local index): wait slot-empty (skip round 0),
    // issue 6 cp.async, then async-arrive on slot-full.
    auto produce = [&](int j) {
        if (j < NCH_H) {
            const int s = j & 3;
            const int r = j >> 2;
            if (r > 0) mbar_wait(sb + 32 + s * 8, (u32)((r & 1) ^ 1));
            const int icg = ic0 + j;
            const u32 sdst = sb + SM_DATA + (u32)s * STAGE;
            const size_t kbase = (size_t)(icg >> 4) * ((size_t)NT * KL)
                               + (size_t)((icg & 15) << 6);
            const __half* pa = gA + kbase;
            const __half* pb = gB + kbase;
            #pragma unroll
            for (int j2 = 0; j2 < 4; ++j2)
                cp16(sdst + sRowA + swzA[j2], pa + j2 * 8);
            #pragma unroll
            for (int j2 = 0; j2 < 2; ++j2)
                cp16(sdst + R_B + sRowB + swzB[j2], pb + j2 * 8);
            cp_arrive(sb + s * 8);
        }
    };

    auto ldsm_kk = [&](u32 base, int kk, int fb) {
        const u32 off = (((u32)(2 * kk) + khalf) ^ l7) << 4;
        const u32 pa = base + raA + off;
        const u32 pb = base + raB + off;
        #pragma unroll
        for (int t = 0; t < 4; ++t) ldsm4(pa + (u32)t * 2048, ah[fb][t]);
        #pragma unroll
        for (int t = 0; t < 2; ++t) ldsm4(pb + (u32)t * 2048, bh[fb][t]);
    };

    // ---- prologue: stage chunks 0..2 of this split ----
    produce(0); produce(1); produce(2);

    #pragma unroll 1
    for (int ic = 0; ic < NCH_H; ++ic) {
        const int s = ic & 3;
        const u32 base = sb + SM_DATA + (u32)s * STAGE;

        // Slot-full wait (cp-arrivals from all 512 threads, issued >=3
        // chunks ago — normally instant).
        mbar_wait(sb + s * 8, (u32)((ic >> 2) & 1));

        ldsm_kk(base, 0, 0);

        // Refill slot (ic+3)%4 = (ic-1)%4; empty-wait inside produce blocks
        // only if some warp is still >1 chunk behind on consumption.
        produce(ic + 3);

        #pragma unroll
        for (int kk = 0; kk < 4; ++kk) {
            const int fb = kk & 1;
            if (kk < 3) ldsm_kk(base, kk + 1, fb ^ 1);   // prefetch next block

            // mt -> j: same-accumulator dep distance = 16 MMAs
            #pragma unroll
            for (int mt = 0; mt < 4; ++mt) {
                #pragma unroll
                for (int j = 0; j < 4; ++j) {
                    const int t = j >> 1, q = j & 1;
                    mma16816(c[mt][j], ah[fb][mt], bh[fb][t][q], bh[fb][t][q + 2]);
                }
            }
        }

        __syncwarp();
        if (lane == 0) mbar_arrive(sb + 32 + s * 8);     // slot consumed
    }

    // ---- epilogue: atomic accumulate (two split contributors per tile) ----
    const int orow = m0 + wm + (lane >> 2);
    const int ocol = n0 + wn + ((lane & 3) << 1);
    #pragma unroll
    for (int mt = 0; mt < 4; ++mt) {
        #pragma unroll
        for (int j = 0; j < 4; ++j) {
            float* p = out + (size_t)(orow + mt * 16) * NT + (ocol + j * 8);
            atomicAdd(p,     c[mt][j][0]);
            atomicAdd(p + 1, c[mt][j][1]);
            atomicAdd(p + (size_t)8 * NT,     c[mt][j][2]);
            atomicAdd(p + (size_t)8 * NT + 1, c[mt][j][3]);
        }
    }
}

extern "C" void kernel_launch(void* const* d_in, const int* in_sizes, int n_in,
                              void* d_out, int out_size)
{
    const float* A = (const float*)d_in[0];   // [8, 4096, 1024]
    const float* W = (const float*)d_in[1];   // [8, 4096, 1024]
    float* out = (float*)d_out;               // [8, 512, 4096] == [4096, 4096]

    cvt_kernel<<<4096, 256>>>(A, W, (float4*)out);

    cudaFuncSetAttribute(gemm_rs_kernel,
                         cudaFuncAttributeMaxDynamicSharedMemorySize, SMEM_TOTAL);
    gemm_rs_kernel<<<1024, 512, SMEM_TOTAL>>>(out);
}